// round 17
// baseline (speedup 1.0000x reference)
#include <cuda_runtime.h>
#include <cstdint>

#define T_ 256
#define D_ 64
#define H_ 256
#define B_ 512
#define ROWSC 8          // batch rows per cluster
#define JH 128           // output columns per CTA
#define NCTA 128
#define THREADS 512      // tid = j0*4 + kq  (kq in lane bits 0-1!)

#define QS 68            // quarter stride for H-vectors (floats): banks 4q, 16B aligned
#define VS 272           // 4*QS
#define XQ 24            // quarter stride for x
#define XS 96            // 4*XQ

// dynamic smem layout (floats)
#define OFF_H    0
#define OFF_ODE  (OFF_H + ROWSC * VS)
#define OFF_A1   (OFF_ODE + ROWSC * VS)
#define OFF_X    (OFF_A1 + ROWSC * VS)
#define OFF_MK   (OFF_X + ROWSC * XS)
#define OFF_DT   (OFF_MK + 8)
#define SMEM_FLOATS (OFF_DT + T_)
#define SMEM_BYTES (SMEM_FLOATS * 4)

// packed: P[k4 * O + o] = float4{ W[o][4k4+0..3] }
__device__ float4 g_w1p[(H_ / 4) * H_];
__device__ float4 g_w2p[(H_ / 4) * H_];
__device__ float4 g_whhp[(H_ / 4) * (3 * H_)];
__device__ float4 g_wihp[(D_ / 4) * (3 * H_)];
__device__ float4 g_woutp[(H_ / 4) * H_];
__device__ float g_dt[T_];

#define N_W1 ((H_ / 4) * H_)
#define N_WHH ((H_ / 4) * (3 * H_))
#define N_WIH ((D_ / 4) * (3 * H_))
#define PK_TOTAL (3 * N_W1 + N_WHH + N_WIH)

__global__ void pack_all_kernel(const float* __restrict__ w1,
                                const float* __restrict__ w2,
                                const float* __restrict__ whh,
                                const float* __restrict__ wih,
                                const float* __restrict__ wout,
                                const float* __restrict__ tps) {
    int idx = blockIdx.x * blockDim.x + threadIdx.x;
    if (idx < T_) {
        g_dt[idx] = (idx == 0) ? (tps[0] - (tps[0] - 0.01f))
                               : (tps[idx] - tps[idx - 1]);
    }
    if (idx >= PK_TOTAL) return;
    const float* src; float4* dst; int O, K, local = idx;
    if (local < N_W1) { src = w1; dst = g_w1p; O = H_; K = H_; }
    else if ((local -= N_W1) < N_W1) { src = w2; dst = g_w2p; O = H_; K = H_; }
    else if ((local -= N_W1) < N_WHH) { src = whh; dst = g_whhp; O = 3 * H_; K = H_; }
    else if ((local -= N_WHH) < N_WIH) { src = wih; dst = g_wihp; O = 3 * H_; K = D_; }
    else { local -= N_WIH; src = wout; dst = g_woutp; O = H_; K = H_; }
    int k4 = local / O;
    int o = local % O;
    const float* s = src + (size_t)o * K + 4 * k4;
    dst[local] = make_float4(s[0], s[1], s[2], s[3]);
}

typedef unsigned long long ull;
__device__ __forceinline__ ull ffma2(ull a, ull b, ull c) {
    ull d; asm("fma.rn.f32x2 %0, %1, %2, %3;" : "=l"(d) : "l"(a), "l"(b), "l"(c)); return d;
}
__device__ __forceinline__ float hadd2(ull v) {
    float2 f; asm("mov.b64 {%0, %1}, %2;" : "=f"(f.x), "=f"(f.y) : "l"(v));
    return f.x + f.y;
}
__device__ __forceinline__ float sigmoidf_(float v) { return 1.0f / (1.0f + expf(-v)); }
// allreduce over the 4 kq lanes (lane bits 0-1)
__device__ __forceinline__ float red4(float v) {
    v += __shfl_xor_sync(0xffffffffu, v, 1);
    v += __shfl_xor_sync(0xffffffffu, v, 2);
    return v;
}

__device__ __forceinline__ void sts_peer_f32(const void* laddr, uint32_t peer, float v) {
    uint32_t la = (uint32_t)__cvta_generic_to_shared(laddr), ra;
    asm("mapa.shared::cluster.u32 %0, %1, %2;" : "=r"(ra) : "r"(la), "r"(peer));
    asm volatile("st.shared::cluster.b32 [%0], %1;" :: "r"(ra), "r"(__float_as_uint(v)) : "memory");
}
__device__ __forceinline__ void cluster_sync_() {
    asm volatile("barrier.cluster.arrive.aligned;" ::: "memory");
    asm volatile("barrier.cluster.wait.aligned;" ::: "memory");
}
__device__ __forceinline__ void cluster_arrive_() {
    asm volatile("barrier.cluster.arrive.aligned;" ::: "memory");
}
__device__ __forceinline__ void cluster_wait_() {
    asm volatile("barrier.cluster.wait.aligned;" ::: "memory");
}

// 8-row GEMM over 16 quads, full weight preload; vbase pre-offset to this thread's quarter.
__device__ __forceinline__ void gemm8f(ull acc[8], const ulonglong2* __restrict__ wp, int wstep,
                                       const float* __restrict__ vbase) {
    ulonglong2 wb[16];
#pragma unroll
    for (int i = 0; i < 16; i++) wb[i] = wp[i * wstep];
#pragma unroll
    for (int kk = 0; kk < 16; kk++) {
        ulonglong2 w = wb[kk];
#pragma unroll
        for (int r = 0; r < 8; r++) {
            ulonglong2 v = *reinterpret_cast<const ulonglong2*>(vbase + r * VS + 4 * kk);
            acc[r] = ffma2(w.x, v.x, acc[r]);
            acc[r] = ffma2(w.y, v.y, acc[r]);
        }
    }
}

__global__ void __launch_bounds__(THREADS, 1) __cluster_dims__(2, 1, 1)
gruode_kernel(const float* __restrict__ x,
              const float* __restrict__ mask,
              const float* __restrict__ b_ih,
              const float* __restrict__ b_hh,
              const float* __restrict__ b1,
              const float* __restrict__ b2,
              const float* __restrict__ b_out,
              float* __restrict__ out) {
    extern __shared__ float sm[];
    float* hbuf = sm + OFF_H;
    float* odebuf = sm + OFF_ODE;
    float* a1buf = sm + OFF_A1;
    float* xbuf = sm + OFF_X;
    float* smk = sm + OFF_MK;
    float* sdt = sm + OFF_DT;

    const ulonglong2* w1u = reinterpret_cast<const ulonglong2*>(g_w1p);
    const ulonglong2* w2u = reinterpret_cast<const ulonglong2*>(g_w2p);
    const ulonglong2* whhu = reinterpret_cast<const ulonglong2*>(g_whhp);
    const ulonglong2* wihu = reinterpret_cast<const ulonglong2*>(g_wihp);
    const ulonglong2* woutu = reinterpret_cast<const ulonglong2*>(g_woutp);

    const int tid = threadIdx.x;
    const int kq = tid & 3;            // lane bits 0-1 -> shuffle-reducible
    const int j0 = tid >> 2;           // 0..127
    uint32_t rank;
    asm("mov.u32 %0, %%cluster_ctarank;" : "=r"(rank));
    const uint32_t peer = rank ^ 1u;
    const int jg = (int)rank * JH + j0;
    const int jphys = (jg >> 6) * QS + (jg & 63);      // physical column offset in quarter layout
    const int row0 = (blockIdx.x >> 1) * ROWSC;
    const int ro0 = 2 * kq, ro1 = 2 * kq + 1;

    for (int idx = tid; idx < ROWSC * VS; idx += THREADS) hbuf[idx] = 0.0f;
    for (int i = tid; i < T_; i += THREADS) sdt[i] = g_dt[i];

    float hc0 = 0.0f, hc1 = 0.0f, hl0 = 0.0f, hl1 = 0.0f;
    float se0 = 0.0f, se1 = 0.0f, ho0 = 0.0f, ho1 = 0.0f;

    const float b1j = b1[jg];
    const float b2j = b2[jg];
    const float brz_r = b_ih[jg] + b_hh[jg];
    const float brz_z = b_ih[H_ + jg] + b_hh[H_ + jg];
    const float bin_ = b_ih[2 * H_ + jg];
    const float bhn = b_hh[2 * H_ + jg];

    // weight bases pre-offset by (k-quarter, column)
    const ulonglong2* w1p = w1u + (kq * 16) * H_ + jg;
    const ulonglong2* w2p = w2u + (kq * 16) * H_ + jg;
    const ulonglong2* whp = whhu + (kq * 16) * (3 * H_) + jg;   // unified stream: i*H_, i=3kk+g
    const ulonglong2* wip = wihu + (kq * 4) * (3 * H_) + jg;
    const ulonglong2* wop = woutu + (kq * 16) * H_ + jg;
    const float* vh = hbuf + kq * QS;
    const float* vode = odebuf + kq * QS;
    const float* va1 = a1buf + kq * QS;
    const float* vx = xbuf + kq * XQ;

    // x/mask staging element for this thread
    const int xr = tid >> 6, xc = tid & 63;
    const int xphys = xr * XS + (xc >> 4) * XQ + (xc & 15);
    const size_t xbase = ((size_t)(row0 + xr) * T_) * D_ + xc;

    xbuf[xphys] = x[xbase];
    if (tid < ROWSC) smk[tid] = mask[(size_t)(row0 + tid) * T_];

    cluster_sync_();

    for (int t = 0; t < T_; t++) {
        // ---- stage 2: a1 = tanh(h @ w1^T + b1) ----
        {
            ull acc[8] = {0ull, 0ull, 0ull, 0ull, 0ull, 0ull, 0ull, 0ull};
            gemm8f(acc, w1p, H_, vh);
            float s0 = 0.0f, s1 = 0.0f;
#pragma unroll
            for (int r = 0; r < 8; r++) {
                float s = red4(hadd2(acc[r]));
                if (r == ro0) s0 = s;
                if (r == ro1) s1 = s;
            }
            float a0 = tanhf(b1j + s0), a1v = tanhf(b1j + s1);
            a1buf[ro0 * VS + jphys] = a0;
            a1buf[ro1 * VS + jphys] = a1v;
            sts_peer_f32(&a1buf[ro0 * VS + jphys], peer, a0);
            sts_peer_f32(&a1buf[ro1 * VS + jphys], peer, a1v);
        }
        cluster_sync_();

        // ---- stage 3: f = a1 @ w2^T + b2 ; euler ; h_ode ----
        {
            ull acc[8] = {0ull, 0ull, 0ull, 0ull, 0ull, 0ull, 0ull, 0ull};
            gemm8f(acc, w2p, H_, va1);
            float s0 = 0.0f, s1 = 0.0f;
#pragma unroll
            for (int r = 0; r < 8; r++) {
                float s = red4(hadd2(acc[r]));
                if (r == ro0) s0 = s;
                if (r == ro1) s1 = s;
            }
            const float dtv = sdt[t];
            float he0 = hc0 + dtv * (b2j + s0);
            float he1 = hc1 + dtv * (b2j + s1);
            ho0 = (se0 > 0.0f) ? he0 : hc0;
            ho1 = (se1 > 0.0f) ? he1 : hc1;
            odebuf[ro0 * VS + jphys] = ho0;
            odebuf[ro1 * VS + jphys] = ho1;
            sts_peer_f32(&odebuf[ro0 * VS + jphys], peer, ho0);
            sts_peer_f32(&odebuf[ro1 * VS + jphys], peer, ho1);
        }
        // ode-exchange barrier window: x-gate GEMM, shuffle-reduced, 6 regs kept
        cluster_arrive_();
        float xgr0, xgr1, xgz0, xgz1, xgi0, xgi1;
        {
            ull xR[8] = {0ull, 0ull, 0ull, 0ull, 0ull, 0ull, 0ull, 0ull};
            ull xZ[8] = {0ull, 0ull, 0ull, 0ull, 0ull, 0ull, 0ull, 0ull};
            ull xI[8] = {0ull, 0ull, 0ull, 0ull, 0ull, 0ull, 0ull, 0ull};
#pragma unroll
            for (int kk = 0; kk < 4; kk++) {
                ulonglong2 wr = wip[kk * (3 * H_)];
                ulonglong2 wz = wip[kk * (3 * H_) + H_];
                ulonglong2 wi = wip[kk * (3 * H_) + 2 * H_];
#pragma unroll
                for (int r = 0; r < 8; r++) {
                    ulonglong2 v = *reinterpret_cast<const ulonglong2*>(vx + r * XS + 4 * kk);
                    xR[r] = ffma2(wr.x, v.x, xR[r]); xR[r] = ffma2(wr.y, v.y, xR[r]);
                    xZ[r] = ffma2(wz.x, v.x, xZ[r]); xZ[r] = ffma2(wz.y, v.y, xZ[r]);
                    xI[r] = ffma2(wi.x, v.x, xI[r]); xI[r] = ffma2(wi.y, v.y, xI[r]);
                }
            }
            xgr0 = xgr1 = xgz0 = xgz1 = xgi0 = xgi1 = 0.0f;
#pragma unroll
            for (int r = 0; r < 8; r++) {
                float sr = red4(hadd2(xR[r]));
                float sz = red4(hadd2(xZ[r]));
                float si = red4(hadd2(xI[r]));
                if (r == ro0) { xgr0 = sr; xgz0 = sz; xgi0 = si; }
                if (r == ro1) { xgr1 = sr; xgz1 = sz; xgi1 = si; }
            }
        }
        cluster_wait_();

        // ---- stage 4: recurrent gates (r,z,n over h_ode), unified depth-8 weight stream ----
        {
            ull aR[8] = {0ull, 0ull, 0ull, 0ull, 0ull, 0ull, 0ull, 0ull};
            ull aZ[8] = {0ull, 0ull, 0ull, 0ull, 0ull, 0ull, 0ull, 0ull};
            ull aN[8] = {0ull, 0ull, 0ull, 0ull, 0ull, 0ull, 0ull, 0ull};
            ulonglong2 wb[8];
#pragma unroll
            for (int i = 0; i < 8; i++) wb[i] = whp[i * H_];
#pragma unroll
            for (int kk = 0; kk < 16; kk++) {
                const int i0 = 3 * kk, i1 = 3 * kk + 1, i2 = 3 * kk + 2;
                ulonglong2 wr = wb[i0 & 7];
                if (i0 + 8 < 48) wb[i0 & 7] = whp[(i0 + 8) * H_];
                ulonglong2 wz = wb[i1 & 7];
                if (i1 + 8 < 48) wb[i1 & 7] = whp[(i1 + 8) * H_];
                ulonglong2 wn = wb[i2 & 7];
                if (i2 + 8 < 48) wb[i2 & 7] = whp[(i2 + 8) * H_];
#pragma unroll
                for (int r = 0; r < 8; r++) {
                    ulonglong2 v = *reinterpret_cast<const ulonglong2*>(vode + r * VS + 4 * kk);
                    aR[r] = ffma2(wr.x, v.x, aR[r]); aR[r] = ffma2(wr.y, v.y, aR[r]);
                    aZ[r] = ffma2(wz.x, v.x, aZ[r]); aZ[r] = ffma2(wz.y, v.y, aZ[r]);
                    aN[r] = ffma2(wn.x, v.x, aN[r]); aN[r] = ffma2(wn.y, v.y, aN[r]);
                }
            }
            float fr0 = 0.0f, fz0 = 0.0f, fn0 = 0.0f, fr1 = 0.0f, fz1 = 0.0f, fn1 = 0.0f;
#pragma unroll
            for (int r = 0; r < 8; r++) {
                float sr = red4(hadd2(aR[r]));
                float sz = red4(hadd2(aZ[r]));
                float sn = red4(hadd2(aN[r]));
                if (r == ro0) { fr0 = sr; fz0 = sz; fn0 = sn; }
                if (r == ro1) { fr1 = sr; fz1 = sz; fn1 = sn; }
            }
            // gates + state update for the 2 owned rows
            {
                float rg0 = sigmoidf_(brz_r + fr0 + xgr0);
                float zg0 = sigmoidf_(brz_z + fz0 + xgz0);
                float ng0 = tanhf(bin_ + xgi0 + rg0 * (bhn + fn0));
                float hr0 = (1.0f - zg0) * ng0 + zg0 * ho0;
                float m0 = smk[ro0];
                float hn0 = (m0 > 0.5f) ? hr0 : ho0;
                hc0 = hn0; hl0 = (m0 > 0.5f) ? hn0 : hl0; se0 = fmaxf(se0, m0);
                hbuf[ro0 * VS + jphys] = hn0;
                sts_peer_f32(&hbuf[ro0 * VS + jphys], peer, hn0);

                float rg1 = sigmoidf_(brz_r + fr1 + xgr1);
                float zg1 = sigmoidf_(brz_z + fz1 + xgz1);
                float ng1 = tanhf(bin_ + xgi1 + rg1 * (bhn + fn1));
                float hr1 = (1.0f - zg1) * ng1 + zg1 * ho1;
                float m1 = smk[ro1];
                float hn1 = (m1 > 0.5f) ? hr1 : ho1;
                hc1 = hn1; hl1 = (m1 > 0.5f) ? hn1 : hl1; se1 = fmaxf(se1, m1);
                hbuf[ro1 * VS + jphys] = hn1;
                sts_peer_f32(&hbuf[ro1 * VS + jphys], peer, hn1);
            }
        }
        // end-of-step barrier window: x_{t+1}/mask prefetch
        cluster_arrive_();
        {
            float xn = 0.0f, mn = 0.0f;
            const bool more = (t + 1 < T_);
            if (more) {
                xn = x[xbase + (size_t)(t + 1) * D_];
                if (tid < ROWSC) mn = mask[(size_t)(row0 + tid) * T_ + (t + 1)];
            }
            cluster_wait_();
            if (more) {
                xbuf[xphys] = xn;
                if (tid < ROWSC) smk[tid] = mn;
            }
        }
    }

    // ---- final projection: out = h_last @ w_out^T + b_out ----
    hbuf[ro0 * VS + jphys] = hl0;
    hbuf[ro1 * VS + jphys] = hl1;
    sts_peer_f32(&hbuf[ro0 * VS + jphys], peer, hl0);
    sts_peer_f32(&hbuf[ro1 * VS + jphys], peer, hl1);
    cluster_sync_();
    {
        ull acc[8] = {0ull, 0ull, 0ull, 0ull, 0ull, 0ull, 0ull, 0ull};
        gemm8f(acc, wop, H_, vh);
        float s0 = 0.0f, s1 = 0.0f;
#pragma unroll
        for (int r = 0; r < 8; r++) {
            float s = red4(hadd2(acc[r]));
            if (r == ro0) s0 = s;
            if (r == ro1) s1 = s;
        }
        const float bo = b_out[jg];
        out[(size_t)(row0 + ro0) * H_ + jg] = bo + s0;
        out[(size_t)(row0 + ro1) * H_ + jg] = bo + s1;
    }
    cluster_sync_();
}

extern "C" void kernel_launch(void* const* d_in, const int* in_sizes, int n_in,
                              void* d_out, int out_size) {
    const float* x     = (const float*)d_in[0];
    const float* tps   = (const float*)d_in[1];
    const float* mask  = (const float*)d_in[2];
    const float* w_ih  = (const float*)d_in[3];
    const float* w_hh  = (const float*)d_in[4];
    const float* b_ih  = (const float*)d_in[5];
    const float* b_hh  = (const float*)d_in[6];
    const float* w1    = (const float*)d_in[7];
    const float* b1    = (const float*)d_in[8];
    const float* w2    = (const float*)d_in[9];
    const float* b2    = (const float*)d_in[10];
    const float* w_out = (const float*)d_in[11];
    const float* b_out = (const float*)d_in[12];
    float* out = (float*)d_out;

    static bool attr_set = false;
    if (!attr_set) {
        cudaFuncSetAttribute(gruode_kernel,
                             cudaFuncAttributeMaxDynamicSharedMemorySize, SMEM_BYTES);
        attr_set = true;
    }

    pack_all_kernel<<<(PK_TOTAL + 255) / 256, 256>>>(w1, w2, w_hh, w_ih, w_out, tps);
    gruode_kernel<<<NCTA, THREADS, SMEM_BYTES>>>(x, mask, b_ih, b_hh, b1, b2, b_out, out);
}